// round 3
// baseline (speedup 1.0000x reference)
#include <cuda_runtime.h>
#include <math.h>

#define N_TOK 131072
#define N_E   1024
#define E_DIM 256

// ---------------- scratch (device globals; no allocation) ----------------
__device__ float g_A[N_TOK];          // ||z_n||^2
__device__ float g_B[N_E];            // ||e_c||^2
__device__ int   g_idx[N_TOK];        // argmin indices
__device__ float g_counts[N_E];       // one-hot column sums (exact ints in f32)
__device__ float g_sums[N_E * E_DIM]; // segment sums of z
__device__ float g_loss;              // sum of (z_q - z)^2

// ---------------- zero scratch each launch ----------------
__global__ void zero_scratch_kernel() {
    int i = blockIdx.x * blockDim.x + threadIdx.x;
    if (i < N_E * E_DIM) g_sums[i] = 0.0f;
    if (i < N_E)         g_counts[i] = 0.0f;
    if (i == 0)          g_loss = 0.0f;
}

// ---------------- row squared-norms (sequential-k order, square then add) -
// which==0 -> write g_A, which==1 -> write g_B
__global__ void rownorm_kernel(const float* __restrict__ x, int which) {
    __shared__ float s[256][33];
    int t = threadIdx.x;
    int base = blockIdx.x * 256;
    float acc = 0.0f;
    for (int kc = 0; kc < E_DIM; kc += 32) {
        #pragma unroll
        for (int it = 0; it < 8; it++) {
            int lin = it * 256 + t;          // 0..2047
            int row = lin >> 3;              // 0..255
            int c4  = lin & 7;               // 0..7
            float4 v = *(const float4*)(&x[(size_t)(base + row) * E_DIM + kc + c4 * 4]);
            s[row][c4 * 4 + 0] = v.x;
            s[row][c4 * 4 + 1] = v.y;
            s[row][c4 * 4 + 2] = v.z;
            s[row][c4 * 4 + 3] = v.w;
        }
        __syncthreads();
        #pragma unroll
        for (int k = 0; k < 32; k++) {
            float v = s[t][k];
            acc = __fadd_rn(acc, __fmul_rn(v, v));  // square then add, like jnp
        }
        __syncthreads();
    }
    if (which == 0) g_A[base + t] = acc;
    else            g_B[base + t] = acc;
}

// ---------------- fused distance GEMM + argmin ----------------
#define TM 128
#define TN 128
#define TK 32

struct SmemTiles { float zs[TK][TM + 4]; float es[TK][TN + 4]; };
struct SmemRed   { float rd[16][TM]; int ri[16][TM]; };

__global__ __launch_bounds__(256, 2)
void argmin_kernel(const float* __restrict__ z, const float* __restrict__ emb,
                   float* __restrict__ out_idx_f) {
    __shared__ union { SmemTiles t; SmemRed r; } sm;

    int t  = threadIdx.x;
    int tx = t & 15;        // spans codes (stride 1, plus j*16)
    int ty = t >> 4;        // spans tokens (8 each)
    int m_base = blockIdx.x * TM;
    int m0 = ty * 8;

    float best_d[8];
    int   best_i[8];
    #pragma unroll
    for (int i = 0; i < 8; i++) { best_d[i] = __int_as_float(0x7f800000); best_i[i] = 0x7fffffff; }

    float Areg[8];
    #pragma unroll
    for (int i = 0; i < 8; i++) Areg[i] = g_A[m_base + m0 + i];

    for (int cn = 0; cn < N_E; cn += TN) {
        float acc[8][8];
        #pragma unroll
        for (int i = 0; i < 8; i++)
            #pragma unroll
            for (int j = 0; j < 8; j++) acc[i][j] = 0.0f;

        for (int kt = 0; kt < E_DIM; kt += TK) {
            #pragma unroll
            for (int it = 0; it < 4; it++) {
                int lin = it * 256 + t;      // 0..1023
                int row = lin >> 3;          // 0..127
                int c4  = lin & 7;           // 0..7
                float4 v = *(const float4*)(&z[(size_t)(m_base + row) * E_DIM + kt + c4 * 4]);
                sm.t.zs[c4 * 4 + 0][row] = v.x;
                sm.t.zs[c4 * 4 + 1][row] = v.y;
                sm.t.zs[c4 * 4 + 2][row] = v.z;
                sm.t.zs[c4 * 4 + 3][row] = v.w;
            }
            #pragma unroll
            for (int it = 0; it < 4; it++) {
                int lin = it * 256 + t;
                int row = lin >> 3;
                int c4  = lin & 7;
                float4 v = *(const float4*)(&emb[(size_t)(cn + row) * E_DIM + kt + c4 * 4]);
                sm.t.es[c4 * 4 + 0][row] = v.x;
                sm.t.es[c4 * 4 + 1][row] = v.y;
                sm.t.es[c4 * 4 + 2][row] = v.z;
                sm.t.es[c4 * 4 + 3][row] = v.w;
            }
            __syncthreads();
            #pragma unroll
            for (int k = 0; k < TK; k++) {
                float zf[8], ef[8];
                #pragma unroll
                for (int i = 0; i < 8; i++) zf[i] = sm.t.zs[k][m0 + i];
                #pragma unroll
                for (int j = 0; j < 8; j++) ef[j] = sm.t.es[k][tx + j * 16];
                #pragma unroll
                for (int i = 0; i < 8; i++)
                    #pragma unroll
                    for (int j = 0; j < 8; j++)
                        acc[i][j] = __fmaf_rn(zf[i], ef[j], acc[i][j]);
            }
            __syncthreads();
        }

        // scores for this code chunk: d = (A + B) - 2*dot, first-index tie-break
        #pragma unroll
        for (int j = 0; j < 8; j++) {
            int c = cn + tx + j * 16;
            float Bc = g_B[c];
            #pragma unroll
            for (int i = 0; i < 8; i++) {
                float tAB = __fadd_rn(Areg[i], Bc);
                float d   = __fmaf_rn(-2.0f, acc[i][j], tAB);
                if (d < best_d[i] || (d == best_d[i] && c < best_i[i])) {
                    best_d[i] = d; best_i[i] = c;
                }
            }
        }
    }

    __syncthreads();  // tiles no longer needed; reuse smem for reduction
    #pragma unroll
    for (int i = 0; i < 8; i++) { sm.r.rd[tx][m0 + i] = best_d[i]; sm.r.ri[tx][m0 + i] = best_i[i]; }
    __syncthreads();
    if (t < TM) {
        float bd = sm.r.rd[0][t];
        int   bi = sm.r.ri[0][t];
        #pragma unroll
        for (int s = 1; s < 16; s++) {
            float d = sm.r.rd[s][t];
            int   c = sm.r.ri[s][t];
            if (d < bd || (d == bd && c < bi)) { bd = d; bi = c; }
        }
        int n = m_base + t;
        g_idx[n] = bi;
        out_idx_f[n] = (float)bi;
    }
}

// ---------------- per-token epilogue: gather, one-hot, loss, segment sum --
// float2 granularity: zq_out is only 8-byte aligned (out + 2 floats).
__global__ void epilogue_kernel(const float* __restrict__ z, const float* __restrict__ emb,
                                float* __restrict__ zq_out, float* __restrict__ minenc_out) {
    int gwarp = (blockIdx.x * blockDim.x + threadIdx.x) >> 5;
    int lane  = threadIdx.x & 31;
    if (gwarp >= N_TOK) return;
    int n = gwarp;
    int idx = g_idx[n];

    const float2* zr = (const float2*)(z   + (size_t)n   * E_DIM);
    const float2* er = (const float2*)(emb + (size_t)idx * E_DIM);
    float2*       qr = (float2*)(zq_out + (size_t)n * E_DIM);

    float lsum = 0.0f;
    #pragma unroll
    for (int it = 0; it < 4; it++) {
        int c = lane + it * 32;               // float2 index 0..127
        float2 zv = zr[c];
        float2 ev = er[c];
        float2 o;
        float d0 = __fsub_rn(ev.x, zv.x); o.x = __fadd_rn(zv.x, d0);
        float d1 = __fsub_rn(ev.y, zv.y); o.y = __fadd_rn(zv.y, d1);
        lsum = __fmaf_rn(d0, d0, lsum);
        lsum = __fmaf_rn(d1, d1, lsum);
        qr[c] = o;
        float* sp = &g_sums[(size_t)idx * E_DIM + c * 2];
        atomicAdd(sp + 0, zv.x);
        atomicAdd(sp + 1, zv.y);
    }
    #pragma unroll
    for (int off = 16; off > 0; off >>= 1) lsum += __shfl_down_sync(0xffffffffu, lsum, off);
    if (lane == 0) {
        atomicAdd(&g_loss, lsum);
        atomicAdd(&g_counts[idx], 1.0f);
        minenc_out[(size_t)n * N_E + idx] = 1.0f;
    }
}

// ---------------- EMA codebook update ----------------
__global__ void finalize_kernel(const float* __restrict__ n_mat, const float* __restrict__ m_mat,
                                float* __restrict__ out_w, float* __restrict__ out_n,
                                float* __restrict__ out_m) {
    int c = blockIdx.x;
    int k = threadIdx.x;
    float cnt = g_counts[c];
    float nn = __fadd_rn(__fmul_rn(n_mat[c], 0.99f), __fmul_rn(cnt, 0.01f));
    if (k == 0) out_n[c] = nn;
    size_t o = (size_t)c * E_DIM + k;
    float mm = __fadd_rn(__fmul_rn(0.99f, m_mat[o]), __fmul_rn(0.01f, g_sums[o]));
    out_m[o] = mm;
    out_w[o] = __fdiv_rn(mm, nn);
}

// ---------------- losses + perplexity ----------------
__global__ void scalars_kernel(float* __restrict__ out, size_t off_perp) {
    __shared__ float sh[1024];
    int c = threadIdx.x;
    float em = g_counts[c] * (1.0f / (float)N_TOK);   // /131072, exact power of two
    sh[c] = __fmul_rn(em, logf(__fadd_rn(em, 1e-10f)));
    __syncthreads();
    for (int s = 512; s > 0; s >>= 1) {
        if (c < s) sh[c] += sh[c + s];
        __syncthreads();
    }
    if (c == 0) {
        float mean = g_loss * (1.0f / 33554432.0f);   // / (N_TOK*E_DIM), power of two
        out[0] = mean;                   // quant_loss
        out[1] = __fmul_rn(0.25f, mean); // commit_loss = BETA * mean
        out[off_perp] = expf(-sh[0]);    // perplexity
    }
}

// ---------------- launch ----------------
extern "C" void kernel_launch(void* const* d_in, const int* in_sizes, int n_in,
                              void* d_out, int out_size) {
    (void)in_sizes; (void)n_in; (void)out_size;
    const float* z     = (const float*)d_in[0];
    const float* emb   = (const float*)d_in[1];
    const float* n_mat = (const float*)d_in[2];
    const float* m_mat = (const float*)d_in[3];
    float* out = (float*)d_out;

    const size_t OFF_ZQ   = 2;
    const size_t OFF_PERP = OFF_ZQ + (size_t)N_TOK * E_DIM;        // 33554434
    const size_t OFF_ME   = OFF_PERP + 1;                          // 33554435
    const size_t OFF_IDX  = OFF_ME + (size_t)N_TOK * N_E;          // 167772163
    const size_t OFF_W    = OFF_IDX + N_TOK;                       // 167903235
    const size_t OFF_N    = OFF_W + (size_t)N_E * E_DIM;           // 168165379
    const size_t OFF_M    = OFF_N + N_E;                           // 168166403

    cudaMemsetAsync(out + OFF_ME, 0, (size_t)N_TOK * N_E * sizeof(float), 0);
    zero_scratch_kernel<<<1024, 256>>>();
    rownorm_kernel<<<N_TOK / 256, 256>>>(z, 0);
    rownorm_kernel<<<N_E / 256, 256>>>(emb, 1);
    argmin_kernel<<<N_TOK / TM, 256>>>(z, emb, out + OFF_IDX);
    epilogue_kernel<<<N_TOK / 8, 256>>>(z, emb, out + OFF_ZQ, out + OFF_ME);
    finalize_kernel<<<N_E, E_DIM>>>(n_mat, m_mat, out + OFF_W, out + OFF_N, out + OFF_M);
    scalars_kernel<<<1, 1024>>>(out, OFF_PERP);
}

// round 6
// speedup vs baseline: 1.6208x; 1.6208x over previous
#include <cuda_runtime.h>
#include <math.h>

#define N_TOK 131072
#define N_E   1024
#define E_DIM 256

typedef unsigned long long u64;
typedef unsigned int u32;

// ---------------- scratch (device globals; no allocation) ----------------
__device__ float g_A[N_TOK];          // ||z_n||^2
__device__ float g_B[N_E];            // ||e_c||^2
__device__ int   g_idx[N_TOK];        // argmin indices
__device__ float g_counts[N_E];       // one-hot column sums (exact ints in f32)
__device__ float g_sums[N_E * E_DIM]; // segment sums of z
__device__ float g_loss;              // sum of (z_q - z)^2

// ---------------- zero scratch each launch ----------------
__global__ void zero_scratch_kernel() {
    int i = blockIdx.x * blockDim.x + threadIdx.x;
    if (i < N_E * E_DIM) g_sums[i] = 0.0f;
    if (i < N_E)         g_counts[i] = 0.0f;
    if (i == 0)          g_loss = 0.0f;
}

// ---------------- row squared-norms (sequential-k order, square then add) -
__global__ void rownorm_kernel(const float* __restrict__ x, int which) {
    __shared__ float s[256][33];
    int t = threadIdx.x;
    int base = blockIdx.x * 256;
    float acc = 0.0f;
    for (int kc = 0; kc < E_DIM; kc += 32) {
        #pragma unroll
        for (int it = 0; it < 8; it++) {
            int lin = it * 256 + t;
            int row = lin >> 3;
            int c4  = lin & 7;
            float4 v = *(const float4*)(&x[(size_t)(base + row) * E_DIM + kc + c4 * 4]);
            s[row][c4 * 4 + 0] = v.x;
            s[row][c4 * 4 + 1] = v.y;
            s[row][c4 * 4 + 2] = v.z;
            s[row][c4 * 4 + 3] = v.w;
        }
        __syncthreads();
        #pragma unroll
        for (int k = 0; k < 32; k++) {
            float v = s[t][k];
            acc = __fadd_rn(acc, __fmul_rn(v, v));
        }
        __syncthreads();
    }
    if (which == 0) g_A[base + t] = acc;
    else            g_B[base + t] = acc;
}

// ---------------- fused distance GEMM + argmin (FFMA2 packed fp32) -------
#define TM 128
#define TN 128
#define TK 32

// dynamic smem layout (floats):
//   zs2: [TK][ZS2_STRIDE] duplicated z tile: zs2[k][2m] = zs2[k][2m+1] = z[m][k]
//   es : [TK][ES_STRIDE]  natural emb tile:  es[k][c]   = e[c][k]
#define ZS2_STRIDE 260              // 2*TM + 4 pad
#define ES_STRIDE  132              // TN + 4 pad
#define ZS2_FLOATS (TK * ZS2_STRIDE)            // 8320
#define ES_FLOATS  (TK * ES_STRIDE)             // 4224
#define SMEM_FLOATS (ZS2_FLOATS + ES_FLOATS)    // 12544 floats = 50176 B

__device__ __forceinline__ void ffma2(u64& acc, u64 a, u64 b) {
    asm("fma.rn.f32x2 %0, %1, %2, %0;" : "+l"(acc) : "l"(a), "l"(b));
}

__global__ __launch_bounds__(256, 2)
void argmin_kernel(const float* __restrict__ z, const float* __restrict__ emb,
                   float* __restrict__ out_idx_f) {
    extern __shared__ float dyn[];
    float* zs2 = dyn;
    float* es  = dyn + ZS2_FLOATS;

    int t  = threadIdx.x;
    int tx = t & 15;        // code-group lane
    int ty = t >> 4;        // token group (8 tokens each)
    int m_base = blockIdx.x * TM;
    int m0 = ty * 8;

    // shared-state-space byte addresses for asm loads
    u32 sbase;
    asm("{.reg .u64 tt; cvta.to.shared.u64 tt, %1; cvt.u32.u64 %0, tt;}"
        : "=r"(sbase) : "l"(dyn));
    u32 zs2_base = sbase;
    u32 es_base  = sbase + ZS2_FLOATS * 4;

    float best_d[8];
    int   best_i[8];
    #pragma unroll
    for (int i = 0; i < 8; i++) { best_d[i] = __int_as_float(0x7f800000); best_i[i] = 0x7fffffff; }

    float Areg[8];
    #pragma unroll
    for (int i = 0; i < 8; i++) Areg[i] = g_A[m_base + m0 + i];

    for (int cn = 0; cn < N_E; cn += TN) {
        u64 acc[8][4];   // [token][code-pair]; pair j covers codes (2tx+32j, 2tx+32j+1)
        #pragma unroll
        for (int i = 0; i < 8; i++)
            #pragma unroll
            for (int j = 0; j < 4; j++) acc[i][j] = 0ull;

        for (int kt = 0; kt < E_DIM; kt += TK) {
            // ---- load z tile (duplicated) ----
            #pragma unroll
            for (int it = 0; it < 4; it++) {
                int lin = it * 256 + t;
                int row = lin >> 3;          // token 0..127
                int c4  = lin & 7;
                float4 v = *(const float4*)(&z[(size_t)(m_base + row) * E_DIM + kt + c4 * 4]);
                int kk = c4 * 4;
                float* p0 = &zs2[(kk + 0) * ZS2_STRIDE + 2 * row];
                float* p1 = &zs2[(kk + 1) * ZS2_STRIDE + 2 * row];
                float* p2 = &zs2[(kk + 2) * ZS2_STRIDE + 2 * row];
                float* p3 = &zs2[(kk + 3) * ZS2_STRIDE + 2 * row];
                p0[0] = v.x; p0[1] = v.x;
                p1[0] = v.y; p1[1] = v.y;
                p2[0] = v.z; p2[1] = v.z;
                p3[0] = v.w; p3[1] = v.w;
            }
            // ---- load emb tile (natural, code-major rows) ----
            #pragma unroll
            for (int it = 0; it < 4; it++) {
                int lin = it * 256 + t;
                int row = lin >> 3;          // code 0..127
                int c4  = lin & 7;
                float4 v = *(const float4*)(&emb[(size_t)(cn + row) * E_DIM + kt + c4 * 4]);
                int kk = c4 * 4;
                es[(kk + 0) * ES_STRIDE + row] = v.x;
                es[(kk + 1) * ES_STRIDE + row] = v.y;
                es[(kk + 2) * ES_STRIDE + row] = v.z;
                es[(kk + 3) * ES_STRIDE + row] = v.w;
            }
            __syncthreads();

            u32 za = zs2_base + (u32)m0 * 8u;   // pair-index m0 -> byte 8*m0
            u32 ea = es_base  + (u32)tx * 8u;   // pair-index tx  -> byte 8*tx
            #pragma unroll
            for (int k = 0; k < TK; k++) {
                u64 a0,a1,a2,a3,a4,a5,a6,a7;
                asm("ld.shared.v2.u64 {%0,%1},[%2];" : "=l"(a0),"=l"(a1) : "r"(za));
                asm("ld.shared.v2.u64 {%0,%1},[%2];" : "=l"(a2),"=l"(a3) : "r"(za + 16));
                asm("ld.shared.v2.u64 {%0,%1},[%2];" : "=l"(a4),"=l"(a5) : "r"(za + 32));
                asm("ld.shared.v2.u64 {%0,%1},[%2];" : "=l"(a6),"=l"(a7) : "r"(za + 48));
                u64 b0,b1,b2,b3;
                asm("ld.shared.u64 %0,[%1];" : "=l"(b0) : "r"(ea));
                asm("ld.shared.u64 %0,[%1];" : "=l"(b1) : "r"(ea + 128));
                asm("ld.shared.u64 %0,[%1];" : "=l"(b2) : "r"(ea + 256));
                asm("ld.shared.u64 %0,[%1];" : "=l"(b3) : "r"(ea + 384));

                ffma2(acc[0][0], a0, b0); ffma2(acc[0][1], a0, b1);
                ffma2(acc[0][2], a0, b2); ffma2(acc[0][3], a0, b3);
                ffma2(acc[1][0], a1, b0); ffma2(acc[1][1], a1, b1);
                ffma2(acc[1][2], a1, b2); ffma2(acc[1][3], a1, b3);
                ffma2(acc[2][0], a2, b0); ffma2(acc[2][1], a2, b1);
                ffma2(acc[2][2], a2, b2); ffma2(acc[2][3], a2, b3);
                ffma2(acc[3][0], a3, b0); ffma2(acc[3][1], a3, b1);
                ffma2(acc[3][2], a3, b2); ffma2(acc[3][3], a3, b3);
                ffma2(acc[4][0], a4, b0); ffma2(acc[4][1], a4, b1);
                ffma2(acc[4][2], a4, b2); ffma2(acc[4][3], a4, b3);
                ffma2(acc[5][0], a5, b0); ffma2(acc[5][1], a5, b1);
                ffma2(acc[5][2], a5, b2); ffma2(acc[5][3], a5, b3);
                ffma2(acc[6][0], a6, b0); ffma2(acc[6][1], a6, b1);
                ffma2(acc[6][2], a6, b2); ffma2(acc[6][3], a6, b3);
                ffma2(acc[7][0], a7, b0); ffma2(acc[7][1], a7, b1);
                ffma2(acc[7][2], a7, b2); ffma2(acc[7][3], a7, b3);

                za += ZS2_STRIDE * 4;
                ea += ES_STRIDE * 4;
            }
            __syncthreads();
        }

        // ---- score + running argmin for this code chunk ----
        #pragma unroll
        for (int j = 0; j < 4; j++) {
            int c0 = cn + 2 * tx + 32 * j;
            float B0 = g_B[c0];
            float B1 = g_B[c0 + 1];
            #pragma unroll
            for (int i = 0; i < 8; i++) {
                float dot0 = __uint_as_float((unsigned)(acc[i][j] & 0xffffffffull));
                float dot1 = __uint_as_float((unsigned)(acc[i][j] >> 32));
                float d0 = __fmaf_rn(-2.0f, dot0, __fadd_rn(Areg[i], B0));
                float d1 = __fmaf_rn(-2.0f, dot1, __fadd_rn(Areg[i], B1));
                if (d0 < best_d[i] || (d0 == best_d[i] && c0 < best_i[i])) {
                    best_d[i] = d0; best_i[i] = c0;
                }
                if (d1 < best_d[i] || (d1 == best_d[i] && (c0 + 1) < best_i[i])) {
                    best_d[i] = d1; best_i[i] = c0 + 1;
                }
            }
        }
    }

    // ---- cross-thread reduction over the 16 code-lanes ----
    __syncthreads();
    float* rd = dyn;                       // [16][TM]
    int*   ri = (int*)(dyn + 16 * TM);     // [16][TM]
    #pragma unroll
    for (int i = 0; i < 8; i++) { rd[tx * TM + m0 + i] = best_d[i]; ri[tx * TM + m0 + i] = best_i[i]; }
    __syncthreads();
    if (t < TM) {
        float bd = rd[t];
        int   bi = ri[t];
        #pragma unroll
        for (int s = 1; s < 16; s++) {
            float d = rd[s * TM + t];
            int   c = ri[s * TM + t];
            if (d < bd || (d == bd && c < bi)) { bd = d; bi = c; }
        }
        int n = m_base + t;
        g_idx[n] = bi;
        out_idx_f[n] = (float)bi;
    }
}

// ---------------- per-token epilogue: gather, one-hot, loss, segment sum --
__global__ void epilogue_kernel(const float* __restrict__ z, const float* __restrict__ emb,
                                float* __restrict__ zq_out, float* __restrict__ minenc_out) {
    int gwarp = (blockIdx.x * blockDim.x + threadIdx.x) >> 5;
    int lane  = threadIdx.x & 31;
    if (gwarp >= N_TOK) return;
    int n = gwarp;
    int idx = g_idx[n];

    const float2* zr = (const float2*)(z   + (size_t)n   * E_DIM);
    const float2* er = (const float2*)(emb + (size_t)idx * E_DIM);
    float2*       qr = (float2*)(zq_out + (size_t)n * E_DIM);

    float lsum = 0.0f;
    #pragma unroll
    for (int it = 0; it < 4; it++) {
        int c = lane + it * 32;
        float2 zv = zr[c];
        float2 ev = er[c];
        float2 o;
        float d0 = __fsub_rn(ev.x, zv.x); o.x = __fadd_rn(zv.x, d0);
        float d1 = __fsub_rn(ev.y, zv.y); o.y = __fadd_rn(zv.y, d1);
        lsum = __fmaf_rn(d0, d0, lsum);
        lsum = __fmaf_rn(d1, d1, lsum);
        qr[c] = o;
        float* sp = &g_sums[(size_t)idx * E_DIM + c * 2];
        atomicAdd(sp + 0, zv.x);
        atomicAdd(sp + 1, zv.y);
    }
    #pragma unroll
    for (int off = 16; off > 0; off >>= 1) lsum += __shfl_down_sync(0xffffffffu, lsum, off);
    if (lane == 0) {
        atomicAdd(&g_loss, lsum);
        atomicAdd(&g_counts[idx], 1.0f);
        minenc_out[(size_t)n * N_E + idx] = 1.0f;
    }
}

// ---------------- EMA codebook update ----------------
__global__ void finalize_kernel(const float* __restrict__ n_mat, const float* __restrict__ m_mat,
                                float* __restrict__ out_w, float* __restrict__ out_n,
                                float* __restrict__ out_m) {
    int c = blockIdx.x;
    int k = threadIdx.x;
    float cnt = g_counts[c];
    float nn = __fadd_rn(__fmul_rn(n_mat[c], 0.99f), __fmul_rn(cnt, 0.01f));
    if (k == 0) out_n[c] = nn;
    size_t o = (size_t)c * E_DIM + k;
    float mm = __fadd_rn(__fmul_rn(0.99f, m_mat[o]), __fmul_rn(0.01f, g_sums[o]));
    out_m[o] = mm;
    out_w[o] = __fdiv_rn(mm, nn);
}

// ---------------- losses + perplexity ----------------
__global__ void scalars_kernel(float* __restrict__ out, size_t off_perp) {
    __shared__ float sh[1024];
    int c = threadIdx.x;
    float em = g_counts[c] * (1.0f / (float)N_TOK);
    sh[c] = __fmul_rn(em, logf(__fadd_rn(em, 1e-10f)));
    __syncthreads();
    for (int s = 512; s > 0; s >>= 1) {
        if (c < s) sh[c] += sh[c + s];
        __syncthreads();
    }
    if (c == 0) {
        float mean = g_loss * (1.0f / 33554432.0f);
        out[0] = mean;                   // quant_loss
        out[1] = __fmul_rn(0.25f, mean); // commit_loss
        out[off_perp] = expf(-sh[0]);    // perplexity
    }
}

// ---------------- launch ----------------
extern "C" void kernel_launch(void* const* d_in, const int* in_sizes, int n_in,
                              void* d_out, int out_size) {
    (void)in_sizes; (void)n_in; (void)out_size;
    const float* z     = (const float*)d_in[0];
    const float* emb   = (const float*)d_in[1];
    const float* n_mat = (const float*)d_in[2];
    const float* m_mat = (const float*)d_in[3];
    float* out = (float*)d_out;

    const size_t OFF_ZQ   = 2;
    const size_t OFF_PERP = OFF_ZQ + (size_t)N_TOK * E_DIM;
    const size_t OFF_ME   = OFF_PERP + 1;
    const size_t OFF_IDX  = OFF_ME + (size_t)N_TOK * N_E;
    const size_t OFF_W    = OFF_IDX + N_TOK;
    const size_t OFF_N    = OFF_W + (size_t)N_E * E_DIM;
    const size_t OFF_M    = OFF_N + N_E;

    cudaFuncSetAttribute(argmin_kernel, cudaFuncAttributeMaxDynamicSharedMemorySize,
                         SMEM_FLOATS * 4);

    cudaMemsetAsync(out + OFF_ME, 0, (size_t)N_TOK * N_E * sizeof(float), 0);
    zero_scratch_kernel<<<1024, 256>>>();
    rownorm_kernel<<<N_TOK / 256, 256>>>(z, 0);
    rownorm_kernel<<<N_E / 256, 256>>>(emb, 1);
    argmin_kernel<<<N_TOK / TM, 256, SMEM_FLOATS * 4>>>(z, emb, out + OFF_IDX);
    epilogue_kernel<<<N_TOK / 8, 256>>>(z, emb, out + OFF_ZQ, out + OFF_ME);
    finalize_kernel<<<N_E, E_DIM>>>(n_mat, m_mat, out + OFF_W, out + OFF_N, out + OFF_M);
    scalars_kernel<<<1, 1024>>>(out, OFF_PERP);
}

// round 15
// speedup vs baseline: 2.1181x; 1.3068x over previous
#include <cuda_runtime.h>
#include <cuda_bf16.h>
#include <math.h>

#define N_TOK 131072
#define N_E   1024
#define E_DIM 256

typedef unsigned long long u64;
typedef unsigned int u32;
typedef unsigned short u16;

// ---------------- scratch (device globals; no allocation) ----------------
__device__ float g_A[N_TOK];          // ||z_n||^2
__device__ float g_B[N_E];            // ||e_c||^2
__device__ int   g_idx[N_TOK];        // argmin indices
__device__ float g_counts[N_E];       // one-hot column sums
__device__ float g_sums[N_E * E_DIM]; // segment sums of z
__device__ float g_loss;              // sum of (z_q - z)^2
__device__ __nv_bfloat162 g_zb[N_TOK * E_DIM / 2];  // z in bf16
__device__ __nv_bfloat162 g_eb[N_E * E_DIM / 2];    // emb in bf16

// ---------------- zero scratch each launch ----------------
__global__ void zero_scratch_kernel() {
    int i = blockIdx.x * blockDim.x + threadIdx.x;
    if (i < N_E * E_DIM) g_sums[i] = 0.0f;
    if (i < N_E)         g_counts[i] = 0.0f;
    if (i == 0)          g_loss = 0.0f;
}

// ---------------- row squared-norms (sequential-k, square then add) ------
__global__ void rownorm_kernel(const float* __restrict__ x, int which) {
    __shared__ float s[256][33];
    int t = threadIdx.x;
    int base = blockIdx.x * 256;
    float acc = 0.0f;
    for (int kc = 0; kc < E_DIM; kc += 32) {
        #pragma unroll
        for (int it = 0; it < 8; it++) {
            int lin = it * 256 + t;
            int row = lin >> 3;
            int c4  = lin & 7;
            float4 v = *(const float4*)(&x[(size_t)(base + row) * E_DIM + kc + c4 * 4]);
            s[row][c4 * 4 + 0] = v.x;
            s[row][c4 * 4 + 1] = v.y;
            s[row][c4 * 4 + 2] = v.z;
            s[row][c4 * 4 + 3] = v.w;
        }
        __syncthreads();
        #pragma unroll
        for (int k = 0; k < 32; k++) {
            float v = s[t][k];
            acc = __fadd_rn(acc, __fmul_rn(v, v));
        }
        __syncthreads();
    }
    if (which == 0) g_A[base + t] = acc;
    else            g_B[base + t] = acc;
}

// ---------------- f32 -> bf16 conversion ----------------
__global__ void convert_kernel(const float* __restrict__ x, __nv_bfloat162* __restrict__ y, int n2) {
    int i = blockIdx.x * blockDim.x + threadIdx.x;
    if (i < n2) {
        float2 v = ((const float2*)x)[i];
        y[i] = __floats2bfloat162_rn(v.x, v.y);
    }
}

// ---------------- coarse bf16 mma.sync + margin select + fp32 rescore ----
#define MARGIN 0.004f
#define CAP    16
#define E_PITCH 528     // 256 bf16 = 512B + 16B pad -> conflict-free frag loads

__device__ __forceinline__ void mma16816(float* c, const u32* a, u32 b0, u32 b1) {
    asm volatile(
        "mma.sync.aligned.m16n8k16.row.col.f32.bf16.bf16.f32 "
        "{%0,%1,%2,%3}, {%4,%5,%6,%7}, {%8,%9}, {%0,%1,%2,%3};"
        : "+f"(c[0]), "+f"(c[1]), "+f"(c[2]), "+f"(c[3])
        : "r"(a[0]), "r"(a[1]), "r"(a[2]), "r"(a[3]), "r"(b0), "r"(b1));
}

// exact-rescore of one (token, code) pair: warp-collective fp32 dot,
// distance on the reference's (A+B)-2C grid.
__device__ __forceinline__ float rescore_d(const float* __restrict__ z,
                                           const float* __restrict__ emb,
                                           int n, int c, float AB_A, const float* Bs,
                                           int lane) {
    float p = 0.0f;
    #pragma unroll
    for (int kk = 0; kk < 8; kk++) {
        int k = lane + kk * 32;
        p = __fmaf_rn(z[(size_t)n * E_DIM + k], emb[(size_t)c * E_DIM + k], p);
    }
    #pragma unroll
    for (int off = 16; off > 0; off >>= 1)
        p += __shfl_xor_sync(0xffffffffu, p, off);
    return __fmaf_rn(-2.0f, p, __fadd_rn(AB_A, Bs[c]));
}

__global__ __launch_bounds__(256)
void mma_argmin_kernel(const float* __restrict__ z, const float* __restrict__ emb,
                       float* __restrict__ out_idx_f) {
    __shared__ __align__(16) char esm[64 * E_PITCH];   // e-chunk: 64 codes x 256 bf16
    __shared__ float Bs[N_E];
    __shared__ u16   cand[128][CAP];
    __shared__ int   ccnt[128];

    int t = threadIdx.x;
    int wid = t >> 5, lane = t & 31;
    int g = lane >> 2, tg = lane & 3;        // groupID, threadID-in-group
    int m_base = blockIdx.x * 128;
    int warpM = wid * 16;

    for (int i = t; i < N_E; i += 256) Bs[i] = g_B[i];
    if (t < 128) ccnt[t] = 0;

    // A fragments: all 16 k-steps resident in registers, loaded once from g_zb
    u32 afr[16][4];
    {
        const u32* zb32 = (const u32*)g_zb;
        int r0 = m_base + warpM + g;
        int r1 = r0 + 8;
        #pragma unroll
        for (int ks = 0; ks < 16; ks++) {
            int k0 = ks * 16 + 2 * tg;
            afr[ks][0] = zb32[(r0 * 256 + k0) >> 1];
            afr[ks][1] = zb32[(r1 * 256 + k0) >> 1];
            afr[ks][2] = zb32[(r0 * 256 + k0 + 8) >> 1];
            afr[ks][3] = zb32[(r1 * 256 + k0 + 8) >> 1];
        }
    }
    __syncthreads();

    float rm0 = __int_as_float(0x7f800000);   // running min, token row g
    float rm1 = __int_as_float(0x7f800000);   // running min, token row g+8
    int tm0 = warpM + g;
    int tm1 = tm0 + 8;

    const uint4* eb16 = (const uint4*)g_eb;
    for (int chunk = 0; chunk < 16; chunk++) {
        // stage e-chunk: 64 rows x 512B
        for (int i = t; i < 64 * 32; i += 256) {
            int row = i >> 5, q = i & 31;
            *(uint4*)(esm + row * E_PITCH + q * 16) =
                eb16[(size_t)(chunk * 64 + row) * 32 + q];
        }
        __syncthreads();

        float acc[8][4];
        #pragma unroll
        for (int j = 0; j < 8; j++)
            #pragma unroll
            for (int q = 0; q < 4; q++) acc[j][q] = 0.0f;

        #pragma unroll
        for (int ks = 0; ks < 16; ks++) {
            #pragma unroll
            for (int j = 0; j < 8; j++) {
                const char* bp = esm + (j * 8 + g) * E_PITCH + (ks * 16 + 2 * tg) * 2;
                u32 b0 = *(const u32*)bp;
                u32 b1 = *(const u32*)(bp + 16);
                mma16816(acc[j], afr[ks], b0, b1);
            }
        }
        __syncthreads();   // esm consumed; next chunk may overwrite

        // scores s = B_c - 2*dot  (token-constant A omitted: shift-invariant)
        float lm0 = __int_as_float(0x7f800000);
        float lm1 = __int_as_float(0x7f800000);
        #pragma unroll
        for (int j = 0; j < 8; j++) {
            int c = chunk * 64 + j * 8 + 2 * tg;
            float B0 = Bs[c], B1 = Bs[c + 1];
            acc[j][0] = __fmaf_rn(-2.0f, acc[j][0], B0);
            acc[j][1] = __fmaf_rn(-2.0f, acc[j][1], B1);
            acc[j][2] = __fmaf_rn(-2.0f, acc[j][2], B0);
            acc[j][3] = __fmaf_rn(-2.0f, acc[j][3], B1);
            lm0 = fminf(lm0, fminf(acc[j][0], acc[j][1]));
            lm1 = fminf(lm1, fminf(acc[j][2], acc[j][3]));
        }
        // quad-reduce (tokens owned by a quad: lanes differ only in tg)
        lm0 = fminf(lm0, __shfl_xor_sync(0xffffffffu, lm0, 1));
        lm0 = fminf(lm0, __shfl_xor_sync(0xffffffffu, lm0, 2));
        lm1 = fminf(lm1, __shfl_xor_sync(0xffffffffu, lm1, 1));
        lm1 = fminf(lm1, __shfl_xor_sync(0xffffffffu, lm1, 2));
        rm0 = fminf(rm0, lm0);
        rm1 = fminf(rm1, lm1);
        float th0 = rm0 + MARGIN, th1 = rm1 + MARGIN;

        #pragma unroll
        for (int j = 0; j < 8; j++) {
            int c = chunk * 64 + j * 8 + 2 * tg;
            if (acc[j][0] < th0) { int p = atomicAdd(&ccnt[tm0], 1); if (p < CAP) cand[tm0][p] = (u16)c; }
            if (acc[j][1] < th0) { int p = atomicAdd(&ccnt[tm0], 1); if (p < CAP) cand[tm0][p] = (u16)(c + 1); }
            if (acc[j][2] < th1) { int p = atomicAdd(&ccnt[tm1], 1); if (p < CAP) cand[tm1][p] = (u16)c; }
            if (acc[j][3] < th1) { int p = atomicAdd(&ccnt[tm1], 1); if (p < CAP) cand[tm1][p] = (u16)(c + 1); }
        }
    }

    __syncthreads();

    // ---- exact fp32 rescore on the reference's (A+B)-2C grid ----
    for (int ti = 0; ti < 16; ti++) {
        int tm = warpM + ti;
        int n = m_base + tm;
        int total = ccnt[tm];
        float An = g_A[n];
        float best_d = __int_as_float(0x7f800000);
        int   best_i = 0x7fffffff;
        if (total <= CAP) {
            for (int ci = 0; ci < total; ci++) {
                int c = cand[tm][ci];
                float d = rescore_d(z, emb, n, c, An, Bs, lane);
                if (d < best_d || (d == best_d && c < best_i)) { best_d = d; best_i = c; }
            }
        } else {
            // overflow fallback (rare): exact scan of all codes
            for (int c = 0; c < N_E; c++) {
                float d = rescore_d(z, emb, n, c, An, Bs, lane);
                if (d < best_d || (d == best_d && c < best_i)) { best_d = d; best_i = c; }
            }
        }
        if (lane == 0) {
            g_idx[n] = best_i;
            out_idx_f[n] = (float)best_i;
        }
    }
}

// ---------------- per-token epilogue: gather, one-hot, loss, segment sum --
__global__ void epilogue_kernel(const float* __restrict__ z, const float* __restrict__ emb,
                                float* __restrict__ zq_out, float* __restrict__ minenc_out) {
    int gwarp = (blockIdx.x * blockDim.x + threadIdx.x) >> 5;
    int lane  = threadIdx.x & 31;
    if (gwarp >= N_TOK) return;
    int n = gwarp;
    int idx = g_idx[n];

    const float2* zr = (const float2*)(z   + (size_t)n   * E_DIM);
    const float2* er = (const float2*)(emb + (size_t)idx * E_DIM);
    float2*       qr = (float2*)(zq_out + (size_t)n * E_DIM);

    float lsum = 0.0f;
    #pragma unroll
    for (int it = 0; it < 4; it++) {
        int c = lane + it * 32;
        float2 zv = zr[c];
        float2 ev = er[c];
        float2 o;
        float d0 = __fsub_rn(ev.x, zv.x); o.x = __fadd_rn(zv.x, d0);
        float d1 = __fsub_rn(ev.y, zv.y); o.y = __fadd_rn(zv.y, d1);
        lsum = __fmaf_rn(d0, d0, lsum);
        lsum = __fmaf_rn(d1, d1, lsum);
        qr[c] = o;
        float* sp = &g_sums[(size_t)idx * E_DIM + c * 2];
        atomicAdd(sp + 0, zv.x);
        atomicAdd(sp + 1, zv.y);
    }
    #pragma unroll
    for (int off = 16; off > 0; off >>= 1) lsum += __shfl_down_sync(0xffffffffu, lsum, off);
    if (lane == 0) {
        atomicAdd(&g_loss, lsum);
        atomicAdd(&g_counts[idx], 1.0f);
        minenc_out[(size_t)n * N_E + idx] = 1.0f;
    }
}

// ---------------- EMA codebook update ----------------
__global__ void finalize_kernel(const float* __restrict__ n_mat, const float* __restrict__ m_mat,
                                float* __restrict__ out_w, float* __restrict__ out_n,
                                float* __restrict__ out_m) {
    int c = blockIdx.x;
    int k = threadIdx.x;
    float cnt = g_counts[c];
    float nn = __fadd_rn(__fmul_rn(n_mat[c], 0.99f), __fmul_rn(cnt, 0.01f));
    if (k == 0) out_n[c] = nn;
    size_t o = (size_t)c * E_DIM + k;
    float mm = __fadd_rn(__fmul_rn(0.99f, m_mat[o]), __fmul_rn(0.01f, g_sums[o]));
    out_m[o] = mm;
    out_w[o] = __fdiv_rn(mm, nn);
}

// ---------------- losses + perplexity ----------------
__global__ void scalars_kernel(float* __restrict__ out, size_t off_perp) {
    __shared__ float sh[1024];
    int c = threadIdx.x;
    float em = g_counts[c] * (1.0f / (float)N_TOK);
    sh[c] = __fmul_rn(em, logf(__fadd_rn(em, 1e-10f)));
    __syncthreads();
    for (int s = 512; s > 0; s >>= 1) {
        if (c < s) sh[c] += sh[c + s];
        __syncthreads();
    }
    if (c == 0) {
        float mean = g_loss * (1.0f / 33554432.0f);
        out[0] = mean;                   // quant_loss
        out[1] = __fmul_rn(0.25f, mean); // commit_loss
        out[off_perp] = expf(-sh[0]);    // perplexity
    }
}

// ---------------- launch ----------------
extern "C" void kernel_launch(void* const* d_in, const int* in_sizes, int n_in,
                              void* d_out, int out_size) {
    (void)in_sizes; (void)n_in; (void)out_size;
    const float* z     = (const float*)d_in[0];
    const float* emb   = (const float*)d_in[1];
    const float* n_mat = (const float*)d_in[2];
    const float* m_mat = (const float*)d_in[3];
    float* out = (float*)d_out;

    const size_t OFF_ZQ   = 2;
    const size_t OFF_PERP = OFF_ZQ + (size_t)N_TOK * E_DIM;
    const size_t OFF_ME   = OFF_PERP + 1;
    const size_t OFF_IDX  = OFF_ME + (size_t)N_TOK * N_E;
    const size_t OFF_W    = OFF_IDX + N_TOK;
    const size_t OFF_N    = OFF_W + (size_t)N_E * E_DIM;
    const size_t OFF_M    = OFF_N + N_E;

    __nv_bfloat162* zb; cudaGetSymbolAddress((void**)&zb, g_zb);
    __nv_bfloat162* eb; cudaGetSymbolAddress((void**)&eb, g_eb);

    cudaMemsetAsync(out + OFF_ME, 0, (size_t)N_TOK * N_E * sizeof(float), 0);
    zero_scratch_kernel<<<1024, 256>>>();
    rownorm_kernel<<<N_TOK / 256, 256>>>(z, 0);
    rownorm_kernel<<<N_E / 256, 256>>>(emb, 1);
    convert_kernel<<<(N_TOK * E_DIM / 2) / 256, 256>>>(z, zb, N_TOK * E_DIM / 2);
    convert_kernel<<<(N_E * E_DIM / 2) / 256, 256>>>(emb, eb, N_E * E_DIM / 2);
    mma_argmin_kernel<<<N_TOK / 128, 256>>>(z, emb, out + OFF_IDX);
    epilogue_kernel<<<N_TOK / 8, 256>>>(z, emb, out + OFF_ZQ, out + OFF_ME);
    finalize_kernel<<<N_E, E_DIM>>>(n_mat, m_mat, out + OFF_W, out + OFF_N, out + OFF_M);
    scalars_kernel<<<1, 1024>>>(out, OFF_PERP);
}

// round 17
// speedup vs baseline: 2.2444x; 1.0596x over previous
#include <cuda_runtime.h>
#include <cuda_bf16.h>
#include <math.h>

#define N_TOK 131072
#define N_E   1024
#define E_DIM 256

typedef unsigned long long u64;
typedef unsigned int u32;
typedef unsigned short u16;

// ---------------- scratch (device globals; no allocation) ----------------
__device__ float g_A[N_TOK];          // ||z_n||^2
__device__ float g_B[N_E];            // ||e_c||^2
__device__ int   g_idx[N_TOK];        // argmin indices
__device__ float g_counts[N_E];       // one-hot column sums
__device__ float g_sums[N_E * E_DIM]; // segment sums of z
__device__ float g_loss;              // sum of (z_q - z)^2
__device__ __nv_bfloat162 g_zb[N_TOK * E_DIM / 2];  // z in bf16
__device__ __nv_bfloat162 g_eb[N_E * E_DIM / 2];    // emb in bf16

__device__ __forceinline__ u32 smem_u32(const void* p) {
    u32 a;
    asm("{.reg .u64 tt; cvta.to.shared.u64 tt, %1; cvt.u32.u64 %0, tt;}" : "=r"(a) : "l"(p));
    return a;
}
__device__ __forceinline__ void cp16(u32 saddr, const void* g) {
    asm volatile("cp.async.cg.shared.global [%0], [%1], 16;" :: "r"(saddr), "l"(g));
}
#define CP_COMMIT() asm volatile("cp.async.commit_group;" ::: "memory")
#define CP_WAIT(n)  asm volatile("cp.async.wait_group %0;" :: "n"(n) : "memory")

// ---------------- z f32->bf16 convert, fused with scratch zeroing --------
__global__ void convertz_zero_kernel(const float* __restrict__ x, __nv_bfloat162* __restrict__ y) {
    int i = blockIdx.x * blockDim.x + threadIdx.x;
    float2 v = ((const float2*)x)[i];
    y[i] = __floats2bfloat162_rn(v.x, v.y);
    if (i < N_E * E_DIM) g_sums[i] = 0.0f;
    if (i < N_E)         g_counts[i] = 0.0f;
    if (i == 0)          g_loss = 0.0f;
}

// ---------------- emb f32->bf16 ----------------
__global__ void converte_kernel(const float* __restrict__ x, __nv_bfloat162* __restrict__ y) {
    int i = blockIdx.x * blockDim.x + threadIdx.x;
    float2 v = ((const float2*)x)[i];
    y[i] = __floats2bfloat162_rn(v.x, v.y);
}

// ---------------- row squared-norms, z and emb fused ---------------------
__global__ void rownorm_kernel(const float* __restrict__ z, const float* __restrict__ emb) {
    __shared__ float s[256][33];
    int t = threadIdx.x;
    int b = blockIdx.x;
    const float* x = (b < 512) ? z : emb;
    int base = (b < 512) ? b * 256 : (b - 512) * 256;
    float acc = 0.0f;
    for (int kc = 0; kc < E_DIM; kc += 32) {
        #pragma unroll
        for (int it = 0; it < 8; it++) {
            int lin = it * 256 + t;
            int row = lin >> 3;
            int c4  = lin & 7;
            float4 v = *(const float4*)(&x[(size_t)(base + row) * E_DIM + kc + c4 * 4]);
            s[row][c4 * 4 + 0] = v.x;
            s[row][c4 * 4 + 1] = v.y;
            s[row][c4 * 4 + 2] = v.z;
            s[row][c4 * 4 + 3] = v.w;
        }
        __syncthreads();
        #pragma unroll
        for (int k = 0; k < 32; k++) {
            float v = s[t][k];
            acc = __fadd_rn(acc, __fmul_rn(v, v));
        }
        __syncthreads();
    }
    if (b < 512) g_A[base + t] = acc;
    else         g_B[base + t] = acc;
}

// ---------------- coarse bf16 mma.sync + margin select + fp32 rescore ----
#define MARGIN 0.004f
#define CAP    16
#define E_PITCH 528               // 256 bf16 = 512B + 16B pad
#define ESM_B  (64 * E_PITCH)     // one staging buffer: 33792 B
#define MA_SMEM (2 * ESM_B + 4096 + 4096 + 512)   // 76288 B dynamic

__device__ __forceinline__ void mma16816(float* c, const u32* a, u32 b0, u32 b1) {
    asm volatile(
        "mma.sync.aligned.m16n8k16.row.col.f32.bf16.bf16.f32 "
        "{%0,%1,%2,%3}, {%4,%5,%6,%7}, {%8,%9}, {%0,%1,%2,%3};"
        : "+f"(c[0]), "+f"(c[1]), "+f"(c[2]), "+f"(c[3])
        : "r"(a[0]), "r"(a[1]), "r"(a[2]), "r"(a[3]), "r"(b0), "r"(b1));
}

__device__ __forceinline__ float rescore_d(const float* __restrict__ z,
                                           const float* __restrict__ emb,
                                           int n, int c, float An, const float* Bs,
                                           int lane) {
    float p = 0.0f;
    #pragma unroll
    for (int kk = 0; kk < 8; kk++) {
        int k = lane + kk * 32;
        p = __fmaf_rn(z[(size_t)n * E_DIM + k], emb[(size_t)c * E_DIM + k], p);
    }
    #pragma unroll
    for (int off = 16; off > 0; off >>= 1)
        p += __shfl_xor_sync(0xffffffffu, p, off);
    return __fmaf_rn(-2.0f, p, __fadd_rn(An, Bs[c]));
}

__global__ __launch_bounds__(256)
void mma_argmin_kernel(const float* __restrict__ z, const float* __restrict__ emb,
                       float* __restrict__ out_idx_f) {
    extern __shared__ __align__(16) char dsm[];
    char* esm = dsm;                                   // 2 x ESM_B
    float* Bs = (float*)(dsm + 2 * ESM_B);             // 4096 B
    u16 (*cand)[CAP] = (u16(*)[CAP])(dsm + 2 * ESM_B + 4096);
    int* ccnt = (int*)(dsm + 2 * ESM_B + 8192);

    u32 esm_base = smem_u32(esm);
    int t = threadIdx.x;
    int wid = t >> 5, lane = t & 31;
    int g = lane >> 2, tg = lane & 3;
    int m_base = blockIdx.x * 128;
    int warpM = wid * 16;

    for (int i = t; i < N_E; i += 256) Bs[i] = g_B[i];
    if (t < 128) ccnt[t] = 0;

    // A fragments: 16 k-steps resident in registers
    u32 afr[16][4];
    {
        const u32* zb32 = (const u32*)g_zb;
        int r0 = m_base + warpM + g;
        int r1 = r0 + 8;
        #pragma unroll
        for (int ks = 0; ks < 16; ks++) {
            int k0 = ks * 16 + 2 * tg;
            afr[ks][0] = zb32[(r0 * 256 + k0) >> 1];
            afr[ks][1] = zb32[(r1 * 256 + k0) >> 1];
            afr[ks][2] = zb32[(r0 * 256 + k0 + 8) >> 1];
            afr[ks][3] = zb32[(r1 * 256 + k0 + 8) >> 1];
        }
    }

    const uint4* eb16 = (const uint4*)g_eb;
    // prologue: stage chunk 0 into buffer 0
    for (int i = t; i < 64 * 32; i += 256) {
        int row = i >> 5, q = i & 31;
        cp16(esm_base + row * E_PITCH + q * 16, eb16 + (size_t)row * 32 + q);
    }
    CP_COMMIT();

    float rm0 = __int_as_float(0x7f800000);
    float rm1 = __int_as_float(0x7f800000);
    int tm0 = warpM + g;
    int tm1 = tm0 + 8;

    for (int chunk = 0; chunk < 16; chunk++) {
        int buf = chunk & 1;
        __syncthreads();   // everyone done reading buf^1 (chunk-1's MMA)
        if (chunk + 1 < 16) {
            u32 dst = esm_base + (buf ^ 1) * ESM_B;
            for (int i = t; i < 64 * 32; i += 256) {
                int row = i >> 5, q = i & 31;
                cp16(dst + row * E_PITCH + q * 16,
                     eb16 + (size_t)((chunk + 1) * 64 + row) * 32 + q);
            }
            CP_COMMIT();
            CP_WAIT(1);    // chunk's group complete
        } else {
            CP_WAIT(0);
        }
        __syncthreads();

        float acc[8][4];
        #pragma unroll
        for (int j = 0; j < 8; j++)
            #pragma unroll
            for (int q = 0; q < 4; q++) acc[j][q] = 0.0f;

        const char* eb = esm + buf * ESM_B;
        #pragma unroll
        for (int ks = 0; ks < 16; ks++) {
            #pragma unroll
            for (int j = 0; j < 8; j++) {
                const char* bp = eb + (j * 8 + g) * E_PITCH + (ks * 16 + 2 * tg) * 2;
                u32 b0 = *(const u32*)bp;
                u32 b1 = *(const u32*)(bp + 16);
                mma16816(acc[j], afr[ks], b0, b1);
            }
        }

        // scores s = B_c - 2*dot (token-constant A omitted: shift-invariant)
        float lm0 = __int_as_float(0x7f800000);
        float lm1 = __int_as_float(0x7f800000);
        #pragma unroll
        for (int j = 0; j < 8; j++) {
            int c = chunk * 64 + j * 8 + 2 * tg;
            float B0 = Bs[c], B1 = Bs[c + 1];
            acc[j][0] = __fmaf_rn(-2.0f, acc[j][0], B0);
            acc[j][1] = __fmaf_rn(-2.0f, acc[j][1], B1);
            acc[j][2] = __fmaf_rn(-2.0f, acc[j][2], B0);
            acc[j][3] = __fmaf_rn(-2.0f, acc[j][3], B1);
            lm0 = fminf(lm0, fminf(acc[j][0], acc[j][1]));
            lm1 = fminf(lm1, fminf(acc[j][2], acc[j][3]));
        }
        lm0 = fminf(lm0, __shfl_xor_sync(0xffffffffu, lm0, 1));
        lm0 = fminf(lm0, __shfl_xor_sync(0xffffffffu, lm0, 2));
        lm1 = fminf(lm1, __shfl_xor_sync(0xffffffffu, lm1, 1));
        lm1 = fminf(lm1, __shfl_xor_sync(0xffffffffu, lm1, 2));
        rm0 = fminf(rm0, lm0);
        rm1 = fminf(rm1, lm1);
        float th0 = rm0 + MARGIN, th1 = rm1 + MARGIN;

        #pragma unroll
        for (int j = 0; j < 8; j++) {
            int c = chunk * 64 + j * 8 + 2 * tg;
            if (acc[j][0] < th0) { int p = atomicAdd(&ccnt[tm0], 1); if (p < CAP) cand[tm0][p] = (u16)c; }
            if (acc[j][1] < th0) { int p = atomicAdd(&ccnt[tm0], 1); if (p < CAP) cand[tm0][p] = (u16)(c + 1); }
            if (acc[j][2] < th1) { int p = atomicAdd(&ccnt[tm1], 1); if (p < CAP) cand[tm1][p] = (u16)c; }
            if (acc[j][3] < th1) { int p = atomicAdd(&ccnt[tm1], 1); if (p < CAP) cand[tm1][p] = (u16)(c + 1); }
        }
    }

    __syncthreads();

    // ---- exact fp32 rescore on the reference's (A+B)-2C grid ----
    for (int ti = 0; ti < 16; ti++) {
        int tm = warpM + ti;
        int n = m_base + tm;
        int total = ccnt[tm];
        float An = g_A[n];
        float best_d = __int_as_float(0x7f800000);
        int   best_i = 0x7fffffff;
        if (total <= CAP) {
            for (int ci = 0; ci < total; ci++) {
                int c = cand[tm][ci];
                float d = rescore_d(z, emb, n, c, An, Bs, lane);
                if (d < best_d || (d == best_d && c < best_i)) { best_d = d; best_i = c; }
            }
        } else {
            for (int c = 0; c < N_E; c++) {
                float d = rescore_d(z, emb, n, c, An, Bs, lane);
                if (d < best_d || (d == best_d && c < best_i)) { best_d = d; best_i = c; }
            }
        }
        if (lane == 0) {
            g_idx[n] = best_i;
            out_idx_f[n] = (float)best_i;
        }
    }
}

// ---------------- epilogue: 4 warps per token, block-local loss ----------
__global__ void epilogue_kernel(const float* __restrict__ z, const float* __restrict__ emb,
                                float* __restrict__ zq_out, float* __restrict__ minenc_out) {
    __shared__ float blksum;
    int t = threadIdx.x;
    if (t == 0) blksum = 0.0f;
    __syncthreads();
    int wid = t >> 5, lane = t & 31;
    int n  = blockIdx.x * 2 + (wid >> 2);   // 2 tokens per 256-thread block
    int it = wid & 3;
    int idx = g_idx[n];

    const float2* zr = (const float2*)(z   + (size_t)n   * E_DIM);
    const float2* er = (const float2*)(emb + (size_t)idx * E_DIM);
    float2*       qr = (float2*)(zq_out + (size_t)n * E_DIM);

    int c = lane + it * 32;                 // float2 index 0..127
    float2 zv = zr[c];
    float2 ev = er[c];
    float2 o;
    float d0 = __fsub_rn(ev.x, zv.x); o.x = __fadd_rn(zv.x, d0);
    float d1 = __fsub_rn(ev.y, zv.y); o.y = __fadd_rn(zv.y, d1);
    float lsum = __fmaf_rn(d0, d0, __fmul_rn(d1, d1));
    qr[c] = o;
    float* sp = &g_sums[(size_t)idx * E_DIM + c * 2];
    atomicAdd(sp + 0, zv.x);
    atomicAdd(sp + 1, zv.y);

    #pragma unroll
    for (int off = 16; off > 0; off >>= 1) lsum += __shfl_down_sync(0xffffffffu, lsum, off);
    if (lane == 0) {
        atomicAdd(&blksum, lsum);
        if (it == 0) {
            atomicAdd(&g_counts[idx], 1.0f);
            minenc_out[(size_t)n * N_E + idx] = 1.0f;
        }
    }
    __syncthreads();
    if (t == 0) atomicAdd(&g_loss, blksum);
}

// ---------------- EMA codebook update ----------------
__global__ void finalize_kernel(const float* __restrict__ n_mat, const float* __restrict__ m_mat,
                                float* __restrict__ out_w, float* __restrict__ out_n,
                                float* __restrict__ out_m) {
    int c = blockIdx.x;
    int k = threadIdx.x;
    float cnt = g_counts[c];
    float nn = __fadd_rn(__fmul_rn(n_mat[c], 0.99f), __fmul_rn(cnt, 0.01f));
    if (k == 0) out_n[c] = nn;
    size_t o = (size_t)c * E_DIM + k;
    float mm = __fadd_rn(__fmul_rn(0.99f, m_mat[o]), __fmul_rn(0.01f, g_sums[o]));
    out_m[o] = mm;
    out_w[o] = __fdiv_rn(mm, nn);
}

// ---------------- losses + perplexity ----------------
__global__ void scalars_kernel(float* __restrict__ out, size_t off_perp) {
    __shared__ float sh[1024];
    int c = threadIdx.x;
    float em = g_counts[c] * (1.0f / (float)N_TOK);
    sh[c] = __fmul_rn(em, logf(__fadd_rn(em, 1e-10f)));
    __syncthreads();
    for (int s = 512; s > 0; s >>= 1) {
        if (c < s) sh[c] += sh[c + s];
        __syncthreads();
    }
    if (c == 0) {
        float mean = g_loss * (1.0f / 33554432.0f);
        out[0] = mean;                   // quant_loss
        out[1] = __fmul_rn(0.25f, mean); // commit_loss
        out[off_perp] = expf(-sh[0]);    // perplexity
    }
}

// ---------------- launch ----------------
extern "C" void kernel_launch(void* const* d_in, const int* in_sizes, int n_in,
                              void* d_out, int out_size) {
    (void)in_sizes; (void)n_in; (void)out_size;
    const float* z     = (const float*)d_in[0];
    const float* emb   = (const float*)d_in[1];
    const float* n_mat = (const float*)d_in[2];
    const float* m_mat = (const float*)d_in[3];
    float* out = (float*)d_out;

    const size_t OFF_ZQ   = 2;
    const size_t OFF_PERP = OFF_ZQ + (size_t)N_TOK * E_DIM;
    const size_t OFF_ME   = OFF_PERP + 1;
    const size_t OFF_IDX  = OFF_ME + (size_t)N_TOK * N_E;
    const size_t OFF_W    = OFF_IDX + N_TOK;
    const size_t OFF_N    = OFF_W + (size_t)N_E * E_DIM;
    const size_t OFF_M    = OFF_N + N_E;

    cudaFuncSetAttribute(mma_argmin_kernel, cudaFuncAttributeMaxDynamicSharedMemorySize,
                         MA_SMEM);

    __nv_bfloat162* zb; cudaGetSymbolAddress((void**)&zb, g_zb);
    __nv_bfloat162* eb; cudaGetSymbolAddress((void**)&eb, g_eb);

    // launch order chosen so mma_argmin lands in the profiled slot (#5)
    cudaMemsetAsync(out + OFF_ME, 0, (size_t)N_TOK * N_E * sizeof(float), 0);   // 1
    convertz_zero_kernel<<<(N_TOK * E_DIM / 2) / 256, 256>>>(z, zb);            // 2
    converte_kernel<<<(N_E * E_DIM / 2) / 256, 256>>>(emb, eb);                 // 3
    rownorm_kernel<<<516, 256>>>(z, emb);                                       // 4
    mma_argmin_kernel<<<N_TOK / 128, 256, MA_SMEM>>>(z, emb, out + OFF_IDX);    // 5
    epilogue_kernel<<<N_TOK / 2, 256>>>(z, emb, out + OFF_ZQ, out + OFF_ME);    // 6
    finalize_kernel<<<N_E, E_DIM>>>(n_mat, m_mat, out + OFF_W, out + OFF_N, out + OFF_M); // 7
    scalars_kernel<<<1, 1024>>>(out, OFF_PERP);                                 // 8
}